// round 13
// baseline (speedup 1.0000x reference)
#include <cuda_runtime.h>
#include <math.h>
#include <float.h>
#include <limits.h>
#include <stdint.h>

#define Lc   2
#define Bc   32
#define Sc   512
#define Dc   512
#define Hc   8
#define DFFc 2048
#define DHc  64
#define KIDX 5
#define BSc  (Bc*Sc)   // 16384

// ---------------- scratch (static device globals; no allocation) ----------------
__device__ float g_x[(size_t)BSc*Dc];
__device__ float g_y[(size_t)BSc*Dc];
__device__ float g_q[(size_t)BSc*Dc];      // q == k (kq_same)
__device__ float g_v[(size_t)BSc*Dc];
__device__ float g_attn[(size_t)BSc*Dc];
__device__ float g_h1[(size_t)BSc*DFFc];
__device__ float g_t2[(size_t)BSc*Dc];

// ---------------- elementwise: x = qemb + pos, y = iemb + pos ----------------
__global__ void addpos_kernel(const float* __restrict__ qe, const float* __restrict__ ie,
                              const float* __restrict__ pe,
                              float* __restrict__ x, float* __restrict__ y)
{
    size_t idx = (size_t)blockIdx.x * blockDim.x + threadIdx.x;
    if (idx >= (size_t)BSc * Dc) return;
    size_t p = idx % ((size_t)Sc * Dc);
    float pv = pe[p];
    x[idx] = qe[idx] + pv;
    y[idx] = ie[idx] + pv;
}

// ---------------- bf16x3 tensor-core GEMM (m16n8k16, single-buffer, 2 blocks/SM) ----------------
__device__ __forceinline__ uint32_t pack_bf16(float lo, float hi) {
    uint32_t r;
    asm("cvt.rn.bf16x2.f32 %0, %1, %2;" : "=r"(r) : "f"(hi), "f"(lo));
    return r;
}

__device__ __forceinline__ void mma_bf16(float c[4], const uint32_t a[4], const uint32_t b[2]) {
    asm volatile(
        "mma.sync.aligned.m16n8k16.row.col.f32.bf16.bf16.f32 "
        "{%0,%1,%2,%3}, {%4,%5,%6,%7}, {%8,%9}, {%0,%1,%2,%3};"
        : "+f"(c[0]), "+f"(c[1]), "+f"(c[2]), "+f"(c[3])
        : "r"(a[0]), "r"(a[1]), "r"(a[2]), "r"(a[3]), "r"(b[0]), "r"(b[1]));
}

__device__ __forceinline__ void split_pair(float x, float y, uint32_t& wb, uint32_t& ws) {
    wb = pack_bf16(x, y);
    float bx = __uint_as_float(wb << 16);
    float by = __uint_as_float(wb & 0xFFFF0000u);
    ws = pack_bf16(x - bx, y - by);
}

#define BM 128
#define BN 128
#define BKb 16

__device__ __forceinline__ void bgemm_body(const float* __restrict__ A,
                                           const float* __restrict__ Bm,
                                           const float* __restrict__ bias,
                                           float* __restrict__ C,
                                           int N, int K, int relu)
{
    // single-buffered: 24 KB/block -> 2 blocks/SM (16 warps) for latency hiding
    __shared__ uint32_t Ab_[BM][12];
    __shared__ uint32_t As_[BM][12];
    __shared__ uint32_t Bb_[BN][12];
    __shared__ uint32_t Bs_[BN][12];

    const int tid  = threadIdx.x;
    const int warp = tid >> 5;
    const int lane = tid & 31;
    const int wm   = warp >> 2;
    const int wn   = warp & 3;
    const int bx = blockIdx.x, by = blockIdx.y;

    const int arow = tid >> 1;
    const int acb  = (tid & 1) * 8;
    const int wc   = (tid & 1) * 4;
    const int kp   = tid & 7;
    const int bn0  = (tid >> 3) * 4;

    const float* Ag = A  + ((size_t)by * BM) * K;
    const float* Bg = Bm + (size_t)bx * BN;

    float c[4][4][4];
    #pragma unroll
    for (int mt = 0; mt < 4; mt++)
        #pragma unroll
        for (int nt = 0; nt < 4; nt++)
            #pragma unroll
            for (int e = 0; e < 4; e++) c[mt][nt][e] = 0.f;

    const int NT = K / BKb;
    float4 a_st[2], b_st[2];

    // prefetch tile 0 into registers
    a_st[0] = *(const float4*)(Ag + (size_t)arow * K + acb);
    a_st[1] = *(const float4*)(Ag + (size_t)arow * K + acb + 4);
    b_st[0] = *(const float4*)(Bg + (size_t)(2 * kp)     * N + bn0);
    b_st[1] = *(const float4*)(Bg + (size_t)(2 * kp + 1) * N + bn0);

    for (int kt = 0; kt < NT; kt++) {
        // deposit staged tile into smem (split big/small)
        {
            uint32_t wb, ws;
            split_pair(a_st[0].x, a_st[0].y, wb, ws);
            Ab_[arow][wc + 0] = wb; As_[arow][wc + 0] = ws;
            split_pair(a_st[0].z, a_st[0].w, wb, ws);
            Ab_[arow][wc + 1] = wb; As_[arow][wc + 1] = ws;
            split_pair(a_st[1].x, a_st[1].y, wb, ws);
            Ab_[arow][wc + 2] = wb; As_[arow][wc + 2] = ws;
            split_pair(a_st[1].z, a_st[1].w, wb, ws);
            Ab_[arow][wc + 3] = wb; As_[arow][wc + 3] = ws;
            const float* r0 = (const float*)&b_st[0];
            const float* r1 = (const float*)&b_st[1];
            #pragma unroll
            for (int j = 0; j < 4; j++) {
                split_pair(r0[j], r1[j], wb, ws);
                Bb_[bn0 + j][kp] = wb;
                Bs_[bn0 + j][kp] = ws;
            }
        }
        __syncthreads();

        // prefetch next tile (LDG latency overlaps MMA below)
        if (kt + 1 < NT) {
            const int k0 = (kt + 1) * BKb;
            a_st[0] = *(const float4*)(Ag + (size_t)arow * K + k0 + acb);
            a_st[1] = *(const float4*)(Ag + (size_t)arow * K + k0 + acb + 4);
            b_st[0] = *(const float4*)(Bg + (size_t)(k0 + 2 * kp)     * N + bn0);
            b_st[1] = *(const float4*)(Bg + (size_t)(k0 + 2 * kp + 1) * N + bn0);
        }

        // fragment loads + 48 MMAs
        {
            const int kq = lane & 3;
            uint32_t ab[4][4], as[4][4], bb[4][2], bs[4][2];
            #pragma unroll
            for (int mt = 0; mt < 4; mt++) {
                const int r = wm * 64 + mt * 16 + (lane >> 2);
                ab[mt][0] = Ab_[r    ][kq    ];
                ab[mt][1] = Ab_[r + 8][kq    ];
                ab[mt][2] = Ab_[r    ][kq + 4];
                ab[mt][3] = Ab_[r + 8][kq + 4];
                as[mt][0] = As_[r    ][kq    ];
                as[mt][1] = As_[r + 8][kq    ];
                as[mt][2] = As_[r    ][kq + 4];
                as[mt][3] = As_[r + 8][kq + 4];
            }
            #pragma unroll
            for (int nt = 0; nt < 4; nt++) {
                const int n = wn * 32 + nt * 8 + (lane >> 2);
                bb[nt][0] = Bb_[n][kq    ];
                bb[nt][1] = Bb_[n][kq + 4];
                bs[nt][0] = Bs_[n][kq    ];
                bs[nt][1] = Bs_[n][kq + 4];
            }
            #pragma unroll
            for (int mt = 0; mt < 4; mt++)
                #pragma unroll
                for (int nt = 0; nt < 4; nt++) {
                    mma_bf16(c[mt][nt], as[mt], bb[nt]);
                    mma_bf16(c[mt][nt], ab[mt], bs[nt]);
                    mma_bf16(c[mt][nt], ab[mt], bb[nt]);
                }
        }
        __syncthreads();
    }

    #pragma unroll
    for (int mt = 0; mt < 4; mt++) {
        const int r0 = by * BM + wm * 64 + mt * 16 + (lane >> 2);
        #pragma unroll
        for (int nt = 0; nt < 4; nt++) {
            const int col = bx * BN + wn * 32 + nt * 8 + 2 * (lane & 3);
            const float b0 = bias[col], b1 = bias[col + 1];
            float2 o0, o1;
            o0.x = c[mt][nt][0] + b0; o0.y = c[mt][nt][1] + b1;
            o1.x = c[mt][nt][2] + b0; o1.y = c[mt][nt][3] + b1;
            if (relu) {
                o0.x = fmaxf(o0.x, 0.f); o0.y = fmaxf(o0.y, 0.f);
                o1.x = fmaxf(o1.x, 0.f); o1.y = fmaxf(o1.y, 0.f);
            }
            *(float2*)(C + (size_t)r0 * N + col)       = o0;
            *(float2*)(C + (size_t)(r0 + 8) * N + col) = o1;
        }
    }
}

__global__ __launch_bounds__(256, 2)
void bgemm_kernel(const float* __restrict__ A, const float* __restrict__ Bm,
                  const float* __restrict__ bias, float* __restrict__ C,
                  int N, int K, int relu)
{
    bgemm_body(A, Bm, bias, C, N, K, relu);
}

// dual GEMM: z=0 -> C0 = A0@B0+bias0 ; z=1 -> C1 = A1@B1+bias1 (same N,K; no relu)
__global__ __launch_bounds__(256, 2)
void bgemm_dual_kernel(const float* __restrict__ A0, const float* __restrict__ B0,
                       const float* __restrict__ bias0, float* __restrict__ C0,
                       const float* __restrict__ A1, const float* __restrict__ B1,
                       const float* __restrict__ bias1, float* __restrict__ C1,
                       int N, int K)
{
    if (blockIdx.z == 0) bgemm_body(A0, B0, bias0, C0, N, K, 0);
    else                 bgemm_body(A1, B1, bias1, C1, N, K, 0);
}

// ---------------- warp-level attention, 2 queries/warp, fast top-k + compact PV ----------------
#define FULLM 0xFFFFFFFFu
#define QPB 16   // queries per block (8 warps x 2)

__device__ __forceinline__ float warp_max(float v) {
    #pragma unroll
    for (int o = 16; o > 0; o >>= 1) v = fmaxf(v, __shfl_xor_sync(FULLM, v, o));
    return v;
}
__device__ __forceinline__ float warp_sum(float v) {
    #pragma unroll
    for (int o = 16; o > 0; o >>= 1) v += __shfl_xor_sync(FULLM, v, o);
    return v;
}

__global__ __launch_bounds__(256)
void attn_kernel(const float* __restrict__ Q, const float* __restrict__ V,
                 float* __restrict__ O)
{
    const int qt   = blockIdx.x;
    const int h    = blockIdx.y;
    const int b    = blockIdx.z;
    const int tid  = threadIdx.x;
    const int warp = tid >> 5;
    const int lane = tid & 31;
    const int i0   = qt * QPB + warp * 2;      // this warp's queries: i0, i0+1

    __shared__ float4 KT4[32][33];             // packed K tile
    __shared__ float4 qs4[QPB][16];

    const size_t base = ((size_t)b * Sc) * Dc + (size_t)h * DHc;

    qs4[warp * 2 + (lane >> 4)][lane & 15] =
        *(const float4*)(Q + base + (size_t)(i0 + (lane >> 4)) * Dc + 4 * (lane & 15));

    float p0[16], p1[16];
    #pragma unroll
    for (int t = 0; t < 16; t++) { p0[t] = -FLT_MAX; p1[t] = -FLT_MAX; }

    const int nk = qt * QPB + QPB - 1;

    const int skey  = tid & 63;
    const int skl   = skey & 31;
    const int shalf = skey >> 5;
    const int sd0   = (tid >> 6) * 16;
    float2* KT2f = (float2*)KT4;

    #pragma unroll
    for (int tt = 0; tt < 8; tt++) {
        if (tt * 64 < nk) {
            const int j0 = tt * 64;
            __syncthreads();
            {
                const float* src = Q + base + (size_t)(j0 + skey) * Dc + sd0;
                #pragma unroll
                for (int f = 0; f < 4; f++) {
                    float4 v = *(const float4*)(src + 4 * f);
                    const int dd = (sd0 >> 1) + 2 * f;
                    KT2f[(dd       * 33 + skl) * 2 + shalf] = make_float2(v.x, v.y);
                    KT2f[((dd + 1) * 33 + skl) * 2 + shalf] = make_float2(v.z, v.w);
                }
            }
            __syncthreads();

            float a00 = 0.f, a01 = 0.f, a10 = 0.f, a11 = 0.f;
            #pragma unroll
            for (int dq = 0; dq < 16; dq++) {
                const float4 qA = qs4[warp * 2    ][dq];
                const float4 qB = qs4[warp * 2 + 1][dq];
                const float4 k0 = KT4[2 * dq    ][lane];
                const float4 k1 = KT4[2 * dq + 1][lane];
                a00 = fmaf(qA.x, k0.x, a00); a00 = fmaf(qA.y, k0.y, a00);
                a00 = fmaf(qA.z, k1.x, a00); a00 = fmaf(qA.w, k1.y, a00);
                a01 = fmaf(qA.x, k0.z, a01); a01 = fmaf(qA.y, k0.w, a01);
                a01 = fmaf(qA.z, k1.z, a01); a01 = fmaf(qA.w, k1.w, a01);
                a10 = fmaf(qB.x, k0.x, a10); a10 = fmaf(qB.y, k0.y, a10);
                a10 = fmaf(qB.z, k1.x, a10); a10 = fmaf(qB.w, k1.y, a10);
                a11 = fmaf(qB.x, k0.z, a11); a11 = fmaf(qB.y, k0.w, a11);
                a11 = fmaf(qB.z, k1.z, a11); a11 = fmaf(qB.w, k1.w, a11);
            }
            const int j1 = j0 + lane, j2 = j0 + lane + 32;
            if (j1 < i0)     p0[2 * tt]     = a00 * 0.125f;
            if (j2 < i0)     p0[2 * tt + 1] = a01 * 0.125f;
            if (j1 < i0 + 1) p1[2 * tt]     = a10 * 0.125f;
            if (j2 < i0 + 1) p1[2 * tt + 1] = a11 * 0.125f;
        }
    }

    // ---- per-query epilogue ----
    #pragma unroll
    for (int qq = 0; qq < 2; qq++) {
        const int i = i0 + qq;
        float p[16];
        #pragma unroll
        for (int t = 0; t < 16; t++) p[t] = qq ? p1[t] : p0[t];

        float* out = O + base + (size_t)i * Dc;
        if (i == 0) {                           // zero_pad row
            out[lane] = 0.f; out[lane + 32] = 0.f;
            continue;
        }

        float lm = -FLT_MAX;
        #pragma unroll
        for (int t = 0; t < 16; t++) lm = fmaxf(lm, p[t]);
        const float m = warp_max(lm);

        float ls = 0.f;
        #pragma unroll
        for (int t = 0; t < 16; t++) { p[t] = __expf(p[t] - m); ls += p[t]; }
        const float invZ = 1.f / warp_sum(ls);
        #pragma unroll
        for (int t = 0; t < 16; t++) p[t] *= invZ;

        float w[16];
        float scale = 1.f;
        if (i > KIDX) {
            float s0 = -1.f, s1 = -1.f, s2 = -1.f, s3 = -1.f, s4 = -1.f;
            #pragma unroll
            for (int t = 0; t < 16; t++) {
                float v = p[t], a;
                a = fmaxf(s0, v); v = fminf(s0, v); s0 = a;
                a = fmaxf(s1, v); v = fminf(s1, v); s1 = a;
                a = fmaxf(s2, v); v = fminf(s2, v); s2 = a;
                a = fmaxf(s3, v); v = fminf(s3, v); s3 = a;
                s4 = fmaxf(s4, v);
            }
            float pmax = 0.f, thresh = 0.f;
            #pragma unroll
            for (int pass = 0; pass < 5; pass++) {
                const float mt = warp_max(s0);
                if (pass == 0) pmax = mt;
                thresh = mt;
                if (pass < 4) {
                    const unsigned blt = __ballot_sync(FULLM, s0 == mt);
                    if (lane == (__ffs(blt) - 1)) {
                        s0 = s1; s1 = s2; s2 = s3; s3 = s4; s4 = -1.f;
                    }
                }
            }
            float lsum = 0.f;
            #pragma unroll
            for (int t = 0; t < 16; t++) {
                w[t] = (p[t] >= thresh) ? __expf(p[t] - pmax) : 0.f;
                lsum += w[t];
            }
            scale = 1.f / warp_sum(lsum);
        } else {
            #pragma unroll
            for (int t = 0; t < 16; t++) w[t] = p[t];
        }

        // ---- compact per-lane (weight, key) pairs: <=3 slots (typical <=1) ----
        float wv0 = 0.f, wv1 = 0.f, wv2 = 0.f;
        int   jj0 = -1,  jj1 = -1,  jj2 = -1;
        int   cnt = 0;
        #pragma unroll
        for (int t = 0; t < 16; t++) {
            if (w[t] > 0.f) {
                const int j = t * 32 + lane;
                if      (cnt == 0) { wv0 = w[t]; jj0 = j; }
                else if (cnt == 1) { wv1 = w[t]; jj1 = j; }
                else if (cnt == 2) { wv2 = w[t]; jj2 = j; }
                cnt++;
            }
        }

        float o0 = 0.f, o1 = 0.f;
        if (__ballot_sync(FULLM, cnt > 3)) {
            #pragma unroll
            for (int t = 0; t < 16; t++) {
                unsigned mask = __ballot_sync(FULLM, w[t] > 0.f);
                while (mask) {
                    const int bit = __ffs(mask) - 1;
                    mask &= mask - 1;
                    const float wj = __shfl_sync(FULLM, w[t], bit);
                    const float* vr = V + base + (size_t)(t * 32 + bit) * Dc;
                    o0 = fmaf(wj, vr[lane],      o0);
                    o1 = fmaf(wj, vr[lane + 32], o1);
                }
            }
        } else {
            unsigned m0 = __ballot_sync(FULLM, jj0 >= 0);
            unsigned m1 = __ballot_sync(FULLM, jj1 >= 0);
            unsigned m2 = __ballot_sync(FULLM, jj2 >= 0);
            while (m0) {
                const int bit = __ffs(m0) - 1; m0 &= m0 - 1;
                const float wj = __shfl_sync(FULLM, wv0, bit);
                const int   j  = __shfl_sync(FULLM, jj0, bit);
                const float* vr = V + base + (size_t)j * Dc;
                o0 = fmaf(wj, vr[lane],      o0);
                o1 = fmaf(wj, vr[lane + 32], o1);
            }
            while (m1) {
                const int bit = __ffs(m1) - 1; m1 &= m1 - 1;
                const float wj = __shfl_sync(FULLM, wv1, bit);
                const int   j  = __shfl_sync(FULLM, jj1, bit);
                const float* vr = V + base + (size_t)j * Dc;
                o0 = fmaf(wj, vr[lane],      o0);
                o1 = fmaf(wj, vr[lane + 32], o1);
            }
            while (m2) {
                const int bit = __ffs(m2) - 1; m2 &= m2 - 1;
                const float wj = __shfl_sync(FULLM, wv2, bit);
                const int   j  = __shfl_sync(FULLM, jj2, bit);
                const float* vr = V + base + (size_t)j * Dc;
                o0 = fmaf(wj, vr[lane],      o0);
                o1 = fmaf(wj, vr[lane + 32], o1);
            }
        }
        out[lane]      = o0 * scale;
        out[lane + 32] = o1 * scale;
    }
}

// ---------------- fused residual + LayerNorm: O = LN(X + R) * g + b ----------------
__global__ void ln_kernel(const float* __restrict__ X, const float* __restrict__ R,
                          const float* __restrict__ g, const float* __restrict__ bt,
                          float* __restrict__ O)
{
    const int row = blockIdx.x;
    const int tid = threadIdx.x;   // 128
    __shared__ float s_red[128];

    const float* xr = X + (size_t)row * Dc;
    const float* rr = R + (size_t)row * Dc;

    float v[4];
    float sum = 0.f, sq = 0.f;
    #pragma unroll
    for (int k = 0; k < 4; k++) {
        float t = xr[tid + k * 128] + rr[tid + k * 128];
        v[k] = t; sum += t; sq += t * t;
    }
    s_red[tid] = sum; __syncthreads();
    for (int s = 64; s > 0; s >>= 1) { if (tid < s) s_red[tid] += s_red[tid + s]; __syncthreads(); }
    float mean = s_red[0] * (1.f / Dc); __syncthreads();
    s_red[tid] = sq; __syncthreads();
    for (int s = 64; s > 0; s >>= 1) { if (tid < s) s_red[tid] += s_red[tid + s]; __syncthreads(); }
    float var = s_red[0] * (1.f / Dc) - mean * mean;
    float rs = rsqrtf(var + 1e-5f);

    #pragma unroll
    for (int k = 0; k < 4; k++) {
        int c = tid + k * 128;
        O[(size_t)row * Dc + c] = (v[k] - mean) * rs * g[c] + bt[c];
    }
}

// ---------------- launch ----------------
extern "C" void kernel_launch(void* const* d_in, const int* in_sizes, int n_in,
                              void* d_out, int out_size)
{
    const float* qe   = (const float*)d_in[0];
    const float* ie   = (const float*)d_in[1];
    const float* pe   = (const float*)d_in[2];
    const float* Wk   = (const float*)d_in[3];
    const float* bk   = (const float*)d_in[4];
    const float* Wv   = (const float*)d_in[5];
    const float* bv   = (const float*)d_in[6];
    const float* Wo   = (const float*)d_in[7];
    const float* bo   = (const float*)d_in[8];
    const float* ln1g = (const float*)d_in[9];
    const float* ln1b = (const float*)d_in[10];
    const float* W1   = (const float*)d_in[11];
    const float* b1   = (const float*)d_in[12];
    const float* W2   = (const float*)d_in[13];
    const float* b2   = (const float*)d_in[14];
    const float* ln2g = (const float*)d_in[15];
    const float* ln2b = (const float*)d_in[16];
    float* out = (float*)d_out;

    float *x, *y, *q, *v, *attn, *h1, *t2;
    cudaGetSymbolAddress((void**)&x,    g_x);
    cudaGetSymbolAddress((void**)&y,    g_y);
    cudaGetSymbolAddress((void**)&q,    g_q);
    cudaGetSymbolAddress((void**)&v,    g_v);
    cudaGetSymbolAddress((void**)&attn, g_attn);
    cudaGetSymbolAddress((void**)&h1,   g_h1);
    cudaGetSymbolAddress((void**)&t2,   g_t2);

    addpos_kernel<<<((size_t)BSc * Dc + 255) / 256, 256>>>(qe, ie, pe, x, y);

    for (int l = 0; l < Lc; l++) {
        const float* Wkl = Wk + (size_t)l * Dc * Dc;
        const float* Wvl = Wv + (size_t)l * Dc * Dc;
        const float* Wol = Wo + (size_t)l * Dc * Dc;
        const float* W1l = W1 + (size_t)l * Dc * DFFc;
        const float* W2l = W2 + (size_t)l * DFFc * Dc;

        // fused Wk || Wv (independent) in one launch for better wave packing
        bgemm_dual_kernel<<<dim3(Dc / BN, BSc / BM, 2), 256>>>(
            x, Wkl, bk + l * Dc, q,
            y, Wvl, bv + l * Dc, v, Dc, Dc);
        attn_kernel<<<dim3(Sc / QPB, Hc, Bc), 256>>>(q, v, attn);
        bgemm_kernel<<<dim3(Dc / BN, BSc / BM), 256>>>(attn, Wol, bo + l * Dc, t2, Dc, Dc, 0);
        ln_kernel<<<BSc, 128>>>(x, t2, ln1g + l * Dc, ln1b + l * Dc, x);
        bgemm_kernel<<<dim3(DFFc / BN, BSc / BM), 256>>>(x, W1l, b1 + l * DFFc, h1, DFFc, Dc, 1);
        bgemm_kernel<<<dim3(Dc / BN, BSc / BM), 256>>>(h1, W2l, b2 + l * Dc, t2, Dc, DFFc, 0);
        float* dst = (l == Lc - 1) ? out : x;
        ln_kernel<<<BSc, 128>>>(x, t2, ln2g + l * Dc, ln2b + l * Dc, dst);
    }
}

// round 17
// speedup vs baseline: 1.0108x; 1.0108x over previous
#include <cuda_runtime.h>
#include <math.h>
#include <float.h>
#include <limits.h>
#include <stdint.h>

#define Lc   2
#define Bc   32
#define Sc   512
#define Dc   512
#define Hc   8
#define DFFc 2048
#define DHc  64
#define KIDX 5
#define BSc  (Bc*Sc)   // 16384

// ---------------- scratch (static device globals; no allocation) ----------------
__device__ float g_x[(size_t)BSc*Dc];
__device__ float g_y[(size_t)BSc*Dc];
__device__ float g_q[(size_t)BSc*Dc];      // q == k (kq_same)
__device__ float g_v[(size_t)BSc*Dc];
__device__ float g_attn[(size_t)BSc*Dc];
__device__ float g_h1[(size_t)BSc*DFFc];
__device__ float g_t2[(size_t)BSc*Dc];

// ---------------- elementwise: x = qemb + pos, y = iemb + pos ----------------
__global__ void addpos_kernel(const float* __restrict__ qe, const float* __restrict__ ie,
                              const float* __restrict__ pe,
                              float* __restrict__ x, float* __restrict__ y)
{
    size_t idx = (size_t)blockIdx.x * blockDim.x + threadIdx.x;
    if (idx >= (size_t)BSc * Dc) return;
    size_t p = idx % ((size_t)Sc * Dc);
    float pv = pe[p];
    x[idx] = qe[idx] + pv;
    y[idx] = ie[idx] + pv;
}

// ---------------- bf16x3 tensor-core GEMM (m16n8k16, double-buffered) ----------------
// MMA issue order: term-major (16 independent accumulators between dependent
// reuses of the same c[mt][nt]) — hides HMMA latency. Per-accumulator addition
// order unchanged: as*bb, ab*bs, ab*bb.
__device__ __forceinline__ uint32_t pack_bf16(float lo, float hi) {
    uint32_t r;
    asm("cvt.rn.bf16x2.f32 %0, %1, %2;" : "=r"(r) : "f"(hi), "f"(lo));
    return r;
}

__device__ __forceinline__ void mma_bf16(float c[4], const uint32_t a[4], const uint32_t b[2]) {
    asm volatile(
        "mma.sync.aligned.m16n8k16.row.col.f32.bf16.bf16.f32 "
        "{%0,%1,%2,%3}, {%4,%5,%6,%7}, {%8,%9}, {%0,%1,%2,%3};"
        : "+f"(c[0]), "+f"(c[1]), "+f"(c[2]), "+f"(c[3])
        : "r"(a[0]), "r"(a[1]), "r"(a[2]), "r"(a[3]), "r"(b[0]), "r"(b[1]));
}

__device__ __forceinline__ void split_pair(float x, float y, uint32_t& wb, uint32_t& ws) {
    wb = pack_bf16(x, y);
    float bx = __uint_as_float(wb << 16);
    float by = __uint_as_float(wb & 0xFFFF0000u);
    ws = pack_bf16(x - bx, y - by);
}

#define BM 128
#define BN 128
#define BKb 16

__device__ __forceinline__ void bgemm_body(const float* __restrict__ A,
                                           const float* __restrict__ Bm,
                                           const float* __restrict__ bias,
                                           float* __restrict__ C,
                                           int N, int K, int relu)
{
    __shared__ uint32_t Ab_[2][BM][12];
    __shared__ uint32_t As_[2][BM][12];
    __shared__ uint32_t Bb_[2][BN][12];
    __shared__ uint32_t Bs_[2][BN][12];

    const int tid  = threadIdx.x;
    const int warp = tid >> 5;
    const int lane = tid & 31;
    const int wm   = warp >> 2;
    const int wn   = warp & 3;
    const int bx = blockIdx.x, by = blockIdx.y;

    const int arow = tid >> 1;
    const int acb  = (tid & 1) * 8;
    const int wc   = (tid & 1) * 4;
    const int kp   = tid & 7;
    const int bn0  = (tid >> 3) * 4;

    const float* Ag = A  + ((size_t)by * BM) * K;
    const float* Bg = Bm + (size_t)bx * BN;

    float c[4][4][4];
    #pragma unroll
    for (int mt = 0; mt < 4; mt++)
        #pragma unroll
        for (int nt = 0; nt < 4; nt++)
            #pragma unroll
            for (int e = 0; e < 4; e++) c[mt][nt][e] = 0.f;

    const int NT = K / BKb;
    float4 a_st[2], b_st[2];

    a_st[0] = *(const float4*)(Ag + (size_t)arow * K + acb);
    a_st[1] = *(const float4*)(Ag + (size_t)arow * K + acb + 4);
    b_st[0] = *(const float4*)(Bg + (size_t)(2 * kp)     * N + bn0);
    b_st[1] = *(const float4*)(Bg + (size_t)(2 * kp + 1) * N + bn0);
    {
        uint32_t wb, ws;
        split_pair(a_st[0].x, a_st[0].y, wb, ws);
        Ab_[0][arow][wc + 0] = wb; As_[0][arow][wc + 0] = ws;
        split_pair(a_st[0].z, a_st[0].w, wb, ws);
        Ab_[0][arow][wc + 1] = wb; As_[0][arow][wc + 1] = ws;
        split_pair(a_st[1].x, a_st[1].y, wb, ws);
        Ab_[0][arow][wc + 2] = wb; As_[0][arow][wc + 2] = ws;
        split_pair(a_st[1].z, a_st[1].w, wb, ws);
        Ab_[0][arow][wc + 3] = wb; As_[0][arow][wc + 3] = ws;
        const float* r0 = (const float*)&b_st[0];
        const float* r1 = (const float*)&b_st[1];
        #pragma unroll
        for (int j = 0; j < 4; j++) {
            split_pair(r0[j], r1[j], wb, ws);
            Bb_[0][bn0 + j][kp] = wb;
            Bs_[0][bn0 + j][kp] = ws;
        }
    }
    __syncthreads();

    for (int kt = 0; kt < NT; kt++) {
        const int cur = kt & 1;

        if (kt + 1 < NT) {
            const int k0 = (kt + 1) * BKb;
            a_st[0] = *(const float4*)(Ag + (size_t)arow * K + k0 + acb);
            a_st[1] = *(const float4*)(Ag + (size_t)arow * K + k0 + acb + 4);
            b_st[0] = *(const float4*)(Bg + (size_t)(k0 + 2 * kp)     * N + bn0);
            b_st[1] = *(const float4*)(Bg + (size_t)(k0 + 2 * kp + 1) * N + bn0);
        }

        {
            const int kq = lane & 3;
            uint32_t ab[4][4], as[4][4], bb[4][2], bs[4][2];
            #pragma unroll
            for (int mt = 0; mt < 4; mt++) {
                const int r = wm * 64 + mt * 16 + (lane >> 2);
                ab[mt][0] = Ab_[cur][r    ][kq    ];
                ab[mt][1] = Ab_[cur][r + 8][kq    ];
                ab[mt][2] = Ab_[cur][r    ][kq + 4];
                ab[mt][3] = Ab_[cur][r + 8][kq + 4];
                as[mt][0] = As_[cur][r    ][kq    ];
                as[mt][1] = As_[cur][r + 8][kq    ];
                as[mt][2] = As_[cur][r    ][kq + 4];
                as[mt][3] = As_[cur][r + 8][kq + 4];
            }
            #pragma unroll
            for (int nt = 0; nt < 4; nt++) {
                const int n = wn * 32 + nt * 8 + (lane >> 2);
                bb[nt][0] = Bb_[cur][n][kq    ];
                bb[nt][1] = Bb_[cur][n][kq + 4];
                bs[nt][0] = Bs_[cur][n][kq    ];
                bs[nt][1] = Bs_[cur][n][kq + 4];
            }
            // term-major issue: 16 independent MMAs between dependent accumulator reuses
            #pragma unroll
            for (int mt = 0; mt < 4; mt++)
                #pragma unroll
                for (int nt = 0; nt < 4; nt++)
                    mma_bf16(c[mt][nt], as[mt], bb[nt]);
            #pragma unroll
            for (int mt = 0; mt < 4; mt++)
                #pragma unroll
                for (int nt = 0; nt < 4; nt++)
                    mma_bf16(c[mt][nt], ab[mt], bs[nt]);
            #pragma unroll
            for (int mt = 0; mt < 4; mt++)
                #pragma unroll
                for (int nt = 0; nt < 4; nt++)
                    mma_bf16(c[mt][nt], ab[mt], bb[nt]);
        }

        if (kt + 1 < NT) {
            const int nxt = cur ^ 1;
            uint32_t wb, ws;
            split_pair(a_st[0].x, a_st[0].y, wb, ws);
            Ab_[nxt][arow][wc + 0] = wb; As_[nxt][arow][wc + 0] = ws;
            split_pair(a_st[0].z, a_st[0].w, wb, ws);
            Ab_[nxt][arow][wc + 1] = wb; As_[nxt][arow][wc + 1] = ws;
            split_pair(a_st[1].x, a_st[1].y, wb, ws);
            Ab_[nxt][arow][wc + 2] = wb; As_[nxt][arow][wc + 2] = ws;
            split_pair(a_st[1].z, a_st[1].w, wb, ws);
            Ab_[nxt][arow][wc + 3] = wb; As_[nxt][arow][wc + 3] = ws;
            const float* r0 = (const float*)&b_st[0];
            const float* r1 = (const float*)&b_st[1];
            #pragma unroll
            for (int j = 0; j < 4; j++) {
                split_pair(r0[j], r1[j], wb, ws);
                Bb_[nxt][bn0 + j][kp] = wb;
                Bs_[nxt][bn0 + j][kp] = ws;
            }
            __syncthreads();
        }
    }

    #pragma unroll
    for (int mt = 0; mt < 4; mt++) {
        const int r0 = by * BM + wm * 64 + mt * 16 + (lane >> 2);
        #pragma unroll
        for (int nt = 0; nt < 4; nt++) {
            const int col = bx * BN + wn * 32 + nt * 8 + 2 * (lane & 3);
            const float b0 = bias[col], b1 = bias[col + 1];
            float2 o0, o1;
            o0.x = c[mt][nt][0] + b0; o0.y = c[mt][nt][1] + b1;
            o1.x = c[mt][nt][2] + b0; o1.y = c[mt][nt][3] + b1;
            if (relu) {
                o0.x = fmaxf(o0.x, 0.f); o0.y = fmaxf(o0.y, 0.f);
                o1.x = fmaxf(o1.x, 0.f); o1.y = fmaxf(o1.y, 0.f);
            }
            *(float2*)(C + (size_t)r0 * N + col)       = o0;
            *(float2*)(C + (size_t)(r0 + 8) * N + col) = o1;
        }
    }
}

__global__ __launch_bounds__(256)
void bgemm_kernel(const float* __restrict__ A, const float* __restrict__ Bm,
                  const float* __restrict__ bias, float* __restrict__ C,
                  int N, int K, int relu)
{
    bgemm_body(A, Bm, bias, C, N, K, relu);
}

// dual GEMM: z=0 -> C0 = A0@B0+bias0 ; z=1 -> C1 = A1@B1+bias1 (same N,K; no relu)
__global__ __launch_bounds__(256)
void bgemm_dual_kernel(const float* __restrict__ A0, const float* __restrict__ B0,
                       const float* __restrict__ bias0, float* __restrict__ C0,
                       const float* __restrict__ A1, const float* __restrict__ B1,
                       const float* __restrict__ bias1, float* __restrict__ C1,
                       int N, int K)
{
    if (blockIdx.z == 0) bgemm_body(A0, B0, bias0, C0, N, K, 0);
    else                 bgemm_body(A1, B1, bias1, C1, N, K, 0);
}

// ---------------- warp-level attention, 2 queries/warp, fast top-k + compact PV ----------------
#define FULLM 0xFFFFFFFFu
#define QPB 16   // queries per block (8 warps x 2)

__device__ __forceinline__ float warp_max(float v) {
    #pragma unroll
    for (int o = 16; o > 0; o >>= 1) v = fmaxf(v, __shfl_xor_sync(FULLM, v, o));
    return v;
}
__device__ __forceinline__ float warp_sum(float v) {
    #pragma unroll
    for (int o = 16; o > 0; o >>= 1) v += __shfl_xor_sync(FULLM, v, o);
    return v;
}

__global__ __launch_bounds__(256)
void attn_kernel(const float* __restrict__ Q, const float* __restrict__ V,
                 float* __restrict__ O)
{
    const int qt   = blockIdx.x;
    const int h    = blockIdx.y;
    const int b    = blockIdx.z;
    const int tid  = threadIdx.x;
    const int warp = tid >> 5;
    const int lane = tid & 31;
    const int i0   = qt * QPB + warp * 2;      // this warp's queries: i0, i0+1

    __shared__ float4 KT4[32][33];             // packed K tile
    __shared__ float4 qs4[QPB][16];

    const size_t base = ((size_t)b * Sc) * Dc + (size_t)h * DHc;

    qs4[warp * 2 + (lane >> 4)][lane & 15] =
        *(const float4*)(Q + base + (size_t)(i0 + (lane >> 4)) * Dc + 4 * (lane & 15));

    float p0[16], p1[16];
    #pragma unroll
    for (int t = 0; t < 16; t++) { p0[t] = -FLT_MAX; p1[t] = -FLT_MAX; }

    const int nk = qt * QPB + QPB - 1;

    const int skey  = tid & 63;
    const int skl   = skey & 31;
    const int shalf = skey >> 5;
    const int sd0   = (tid >> 6) * 16;
    float2* KT2f = (float2*)KT4;

    #pragma unroll
    for (int tt = 0; tt < 8; tt++) {
        if (tt * 64 < nk) {
            const int j0 = tt * 64;
            __syncthreads();
            {
                const float* src = Q + base + (size_t)(j0 + skey) * Dc + sd0;
                #pragma unroll
                for (int f = 0; f < 4; f++) {
                    float4 v = *(const float4*)(src + 4 * f);
                    const int dd = (sd0 >> 1) + 2 * f;
                    KT2f[(dd       * 33 + skl) * 2 + shalf] = make_float2(v.x, v.y);
                    KT2f[((dd + 1) * 33 + skl) * 2 + shalf] = make_float2(v.z, v.w);
                }
            }
            __syncthreads();

            float a00 = 0.f, a01 = 0.f, a10 = 0.f, a11 = 0.f;
            #pragma unroll
            for (int dq = 0; dq < 16; dq++) {
                const float4 qA = qs4[warp * 2    ][dq];
                const float4 qB = qs4[warp * 2 + 1][dq];
                const float4 k0 = KT4[2 * dq    ][lane];
                const float4 k1 = KT4[2 * dq + 1][lane];
                a00 = fmaf(qA.x, k0.x, a00); a00 = fmaf(qA.y, k0.y, a00);
                a00 = fmaf(qA.z, k1.x, a00); a00 = fmaf(qA.w, k1.y, a00);
                a01 = fmaf(qA.x, k0.z, a01); a01 = fmaf(qA.y, k0.w, a01);
                a01 = fmaf(qA.z, k1.z, a01); a01 = fmaf(qA.w, k1.w, a01);
                a10 = fmaf(qB.x, k0.x, a10); a10 = fmaf(qB.y, k0.y, a10);
                a10 = fmaf(qB.z, k1.x, a10); a10 = fmaf(qB.w, k1.y, a10);
                a11 = fmaf(qB.x, k0.z, a11); a11 = fmaf(qB.y, k0.w, a11);
                a11 = fmaf(qB.z, k1.z, a11); a11 = fmaf(qB.w, k1.w, a11);
            }
            const int j1 = j0 + lane, j2 = j0 + lane + 32;
            if (j1 < i0)     p0[2 * tt]     = a00 * 0.125f;
            if (j2 < i0)     p0[2 * tt + 1] = a01 * 0.125f;
            if (j1 < i0 + 1) p1[2 * tt]     = a10 * 0.125f;
            if (j2 < i0 + 1) p1[2 * tt + 1] = a11 * 0.125f;
        }
    }

    // ---- per-query epilogue ----
    #pragma unroll
    for (int qq = 0; qq < 2; qq++) {
        const int i = i0 + qq;
        float p[16];
        #pragma unroll
        for (int t = 0; t < 16; t++) p[t] = qq ? p1[t] : p0[t];

        float* out = O + base + (size_t)i * Dc;
        if (i == 0) {                           // zero_pad row
            out[lane] = 0.f; out[lane + 32] = 0.f;
            continue;
        }

        float lm = -FLT_MAX;
        #pragma unroll
        for (int t = 0; t < 16; t++) lm = fmaxf(lm, p[t]);
        const float m = warp_max(lm);

        float ls = 0.f;
        #pragma unroll
        for (int t = 0; t < 16; t++) { p[t] = __expf(p[t] - m); ls += p[t]; }
        const float invZ = 1.f / warp_sum(ls);
        #pragma unroll
        for (int t = 0; t < 16; t++) p[t] *= invZ;

        float w[16];
        float scale = 1.f;
        if (i > KIDX) {
            float s0 = -1.f, s1 = -1.f, s2 = -1.f, s3 = -1.f, s4 = -1.f;
            #pragma unroll
            for (int t = 0; t < 16; t++) {
                float v = p[t], a;
                a = fmaxf(s0, v); v = fminf(s0, v); s0 = a;
                a = fmaxf(s1, v); v = fminf(s1, v); s1 = a;
                a = fmaxf(s2, v); v = fminf(s2, v); s2 = a;
                a = fmaxf(s3, v); v = fminf(s3, v); s3 = a;
                s4 = fmaxf(s4, v);
            }
            float pmax = 0.f, thresh = 0.f;
            #pragma unroll
            for (int pass = 0; pass < 5; pass++) {
                const float mt = warp_max(s0);
                if (pass == 0) pmax = mt;
                thresh = mt;
                if (pass < 4) {
                    const unsigned blt = __ballot_sync(FULLM, s0 == mt);
                    if (lane == (__ffs(blt) - 1)) {
                        s0 = s1; s1 = s2; s2 = s3; s3 = s4; s4 = -1.f;
                    }
                }
            }
            float lsum = 0.f;
            #pragma unroll
            for (int t = 0; t < 16; t++) {
                w[t] = (p[t] >= thresh) ? __expf(p[t] - pmax) : 0.f;
                lsum += w[t];
            }
            scale = 1.f / warp_sum(lsum);
        } else {
            #pragma unroll
            for (int t = 0; t < 16; t++) w[t] = p[t];
        }

        // ---- compact per-lane (weight, key) pairs: <=3 slots (typical <=1) ----
        float wv0 = 0.f, wv1 = 0.f, wv2 = 0.f;
        int   jj0 = -1,  jj1 = -1,  jj2 = -1;
        int   cnt = 0;
        #pragma unroll
        for (int t = 0; t < 16; t++) {
            if (w[t] > 0.f) {
                const int j = t * 32 + lane;
                if      (cnt == 0) { wv0 = w[t]; jj0 = j; }
                else if (cnt == 1) { wv1 = w[t]; jj1 = j; }
                else if (cnt == 2) { wv2 = w[t]; jj2 = j; }
                cnt++;
            }
        }

        float o0 = 0.f, o1 = 0.f;
        if (__ballot_sync(FULLM, cnt > 3)) {
            #pragma unroll
            for (int t = 0; t < 16; t++) {
                unsigned mask = __ballot_sync(FULLM, w[t] > 0.f);
                while (mask) {
                    const int bit = __ffs(mask) - 1;
                    mask &= mask - 1;
                    const float wj = __shfl_sync(FULLM, w[t], bit);
                    const float* vr = V + base + (size_t)(t * 32 + bit) * Dc;
                    o0 = fmaf(wj, vr[lane],      o0);
                    o1 = fmaf(wj, vr[lane + 32], o1);
                }
            }
        } else {
            unsigned m0 = __ballot_sync(FULLM, jj0 >= 0);
            unsigned m1 = __ballot_sync(FULLM, jj1 >= 0);
            unsigned m2 = __ballot_sync(FULLM, jj2 >= 0);
            while (m0) {
                const int bit = __ffs(m0) - 1; m0 &= m0 - 1;
                const float wj = __shfl_sync(FULLM, wv0, bit);
                const int   j  = __shfl_sync(FULLM, jj0, bit);
                const float* vr = V + base + (size_t)j * Dc;
                o0 = fmaf(wj, vr[lane],      o0);
                o1 = fmaf(wj, vr[lane + 32], o1);
            }
            while (m1) {
                const int bit = __ffs(m1) - 1; m1 &= m1 - 1;
                const float wj = __shfl_sync(FULLM, wv1, bit);
                const int   j  = __shfl_sync(FULLM, jj1, bit);
                const float* vr = V + base + (size_t)j * Dc;
                o0 = fmaf(wj, vr[lane],      o0);
                o1 = fmaf(wj, vr[lane + 32], o1);
            }
            while (m2) {
                const int bit = __ffs(m2) - 1; m2 &= m2 - 1;
                const float wj = __shfl_sync(FULLM, wv2, bit);
                const int   j  = __shfl_sync(FULLM, jj2, bit);
                const float* vr = V + base + (size_t)j * Dc;
                o0 = fmaf(wj, vr[lane],      o0);
                o1 = fmaf(wj, vr[lane + 32], o1);
            }
        }
        out[lane]      = o0 * scale;
        out[lane + 32] = o1 * scale;
    }
}

// ---------------- fused residual + LayerNorm: O = LN(X + R) * g + b ----------------
__global__ void ln_kernel(const float* __restrict__ X, const float* __restrict__ R,
                          const float* __restrict__ g, const float* __restrict__ bt,
                          float* __restrict__ O)
{
    const int row = blockIdx.x;
    const int tid = threadIdx.x;   // 128
    __shared__ float s_red[128];

    const float* xr = X + (size_t)row * Dc;
    const float* rr = R + (size_t)row * Dc;

    float v[4];
    float sum = 0.f, sq = 0.f;
    #pragma unroll
    for (int k = 0; k < 4; k++) {
        float t = xr[tid + k * 128] + rr[tid + k * 128];
        v[k] = t; sum += t; sq += t * t;
    }
    s_red[tid] = sum; __syncthreads();
    for (int s = 64; s > 0; s >>= 1) { if (tid < s) s_red[tid] += s_red[tid + s]; __syncthreads(); }
    float mean = s_red[0] * (1.f / Dc); __syncthreads();
    s_red[tid] = sq; __syncthreads();
    for (int s = 64; s > 0; s >>= 1) { if (tid < s) s_red[tid] += s_red[tid + s]; __syncthreads(); }
    float var = s_red[0] * (1.f / Dc) - mean * mean;
    float rs = rsqrtf(var + 1e-5f);

    #pragma unroll
    for (int k = 0; k < 4; k++) {
        int c = tid + k * 128;
        O[(size_t)row * Dc + c] = (v[k] - mean) * rs * g[c] + bt[c];
    }
}

// ---------------- launch ----------------
extern "C" void kernel_launch(void* const* d_in, const int* in_sizes, int n_in,
                              void* d_out, int out_size)
{
    const float* qe   = (const float*)d_in[0];
    const float* ie   = (const float*)d_in[1];
    const float* pe   = (const float*)d_in[2];
    const float* Wk   = (const float*)d_in[3];
    const float* bk   = (const float*)d_in[4];
    const float* Wv   = (const float*)d_in[5];
    const float* bv   = (const float*)d_in[6];
    const float* Wo   = (const float*)d_in[7];
    const float* bo   = (const float*)d_in[8];
    const float* ln1g = (const float*)d_in[9];
    const float* ln1b = (const float*)d_in[10];
    const float* W1   = (const float*)d_in[11];
    const float* b1   = (const float*)d_in[12];
    const float* W2   = (const float*)d_in[13];
    const float* b2   = (const float*)d_in[14];
    const float* ln2g = (const float*)d_in[15];
    const float* ln2b = (const float*)d_in[16];
    float* out = (float*)d_out;

    float *x, *y, *q, *v, *attn, *h1, *t2;
    cudaGetSymbolAddress((void**)&x,    g_x);
    cudaGetSymbolAddress((void**)&y,    g_y);
    cudaGetSymbolAddress((void**)&q,    g_q);
    cudaGetSymbolAddress((void**)&v,    g_v);
    cudaGetSymbolAddress((void**)&attn, g_attn);
    cudaGetSymbolAddress((void**)&h1,   g_h1);
    cudaGetSymbolAddress((void**)&t2,   g_t2);

    addpos_kernel<<<((size_t)BSc * Dc + 255) / 256, 256>>>(qe, ie, pe, x, y);

    for (int l = 0; l < Lc; l++) {
        const float* Wkl = Wk + (size_t)l * Dc * Dc;
        const float* Wvl = Wv + (size_t)l * Dc * Dc;
        const float* Wol = Wo + (size_t)l * Dc * Dc;
        const float* W1l = W1 + (size_t)l * Dc * DFFc;
        const float* W2l = W2 + (size_t)l * DFFc * Dc;

        // fused Wk || Wv (independent) in one launch for better wave packing
        bgemm_dual_kernel<<<dim3(Dc / BN, BSc / BM, 2), 256>>>(
            x, Wkl, bk + l * Dc, q,
            y, Wvl, bv + l * Dc, v, Dc, Dc);
        attn_kernel<<<dim3(Sc / QPB, Hc, Bc), 256>>>(q, v, attn);
        bgemm_kernel<<<dim3(Dc / BN, BSc / BM), 256>>>(attn, Wol, bo + l * Dc, t2, Dc, Dc, 0);
        ln_kernel<<<BSc, 128>>>(x, t2, ln1g + l * Dc, ln1b + l * Dc, x);
        bgemm_kernel<<<dim3(DFFc / BN, BSc / BM), 256>>>(x, W1l, b1 + l * DFFc, h1, DFFc, Dc, 1);
        bgemm_kernel<<<dim3(Dc / BN, BSc / BM), 256>>>(h1, W2l, b2 + l * Dc, t2, Dc, DFFc, 0);
        float* dst = (l == Lc - 1) ? out : x;
        ln_kernel<<<BSc, 128>>>(x, t2, ln2g + l * Dc, ln2b + l * Dc, dst);
    }
}